// round 5
// baseline (speedup 1.0000x reference)
#include <cuda_runtime.h>
#include <cuda_fp16.h>
#include <math.h>
#include <stdint.h>

#define IN_DIM 128
#define HID 256
#define EMB 128
#define MAXN 50000
#define MAXE 800000

// ---------------- scratch (device globals; no allocation) ----------------
__device__ int    d_degi[MAXN];
__device__ float  d_dinv[MAXN];
__device__ int    d_off[MAXN + 1];
__device__ int    d_cursor[MAXN];
__device__ int    d_elist[MAXE];
__device__ __half d_xh[MAXN * IN_DIM];    // x in fp16
__device__ float  d_aggx[MAXN * IN_DIM];  // aggregated x (fp32)
__device__ float  d_h1[MAXN * HID];       // relu(aggx@W1+b1)
__device__ __half d_h2[MAXN * EMB];       // h1@W2 in fp16
__device__ float  d_agg2[MAXN * EMB];     // final H (fp32)
__device__ float  d_gsum[EMB];
__device__ float4 d_pnode[MAXN];

__device__ __forceinline__ float warp_sum(float v) {
    #pragma unroll
    for (int o = 16; o; o >>= 1) v += __shfl_down_sync(0xffffffffu, v, o);
    return v;
}

__device__ __forceinline__ uint32_t f2tf32(float f) {
    uint32_t r;
    asm("cvt.rna.tf32.f32 %0, %1;" : "=r"(r) : "f"(f));
    return r;
}

// ---------------- prep: zero deg/gsum + convert x -> fp16 ----------------
__global__ void k_prep(const float* __restrict__ x, int n) {
    int i = blockIdx.x * blockDim.x + threadIdx.x;
    int total = n * (IN_DIM / 2);             // half2 elements
    if (i < total) {
        float2 v = ((const float2*)x)[i];
        ((__half2*)d_xh)[i] = __floats2half2_rn(v.x, v.y);
    }
    if (i < n) d_degi[i] = 0;
    if (i < EMB) d_gsum[i] = 0.f;
}

__global__ void k_deg(const int* __restrict__ dst, int E) {
    int i = blockIdx.x * blockDim.x + threadIdx.x;
    if (i < E) atomicAdd(&d_degi[dst[i]], 1);
}

// ---------------- single-block scan + dinv + cursor init ----------------
__global__ void k_scan(int n, int E, int chunk) {
    __shared__ int sm[1024];
    int t = threadIdx.x;
    int lo = t * chunk;
    int hi = min(n, lo + chunk);
    int sum = 0;
    for (int i = lo; i < hi; i++) sum += d_degi[i];
    sm[t] = sum;
    __syncthreads();
    #pragma unroll
    for (int o = 1; o < 1024; o <<= 1) {
        int add = (t >= o) ? sm[t - o] : 0;
        __syncthreads();
        sm[t] += add;
        __syncthreads();
    }
    int run = sm[t] - sum;  // exclusive prefix
    for (int i = lo; i < hi; i++) {
        int dg = d_degi[i];
        d_off[i] = run;
        d_cursor[i] = run;
        d_dinv[i] = rsqrtf((float)dg + 1.0f);
        run += dg;
    }
    if (t == 0) d_off[n] = E;
}

__global__ void k_fill(const int* __restrict__ src, const int* __restrict__ dst, int E) {
    int i = blockIdx.x * blockDim.x + threadIdx.x;
    if (i >= E) return;
    int d = dst[i];
    int pos = atomicAdd(&d_cursor[d], 1);
    d_elist[pos] = src[i];
}

// ---------------- gather 1: warp per node, fp16 in, fp32 out ----------------
__global__ void k_gather1(int n) {
    int warp = (blockIdx.x * blockDim.x + threadIdx.x) >> 5;
    int lane = threadIdx.x & 31;
    if (warp >= n) return;
    float dv = d_dinv[warp];
    float d2 = dv * dv;
    const __half2* Hv = (const __half2*)d_xh;
    __half2 a0 = Hv[(size_t)warp * 64 + lane];
    __half2 a1 = Hv[(size_t)warp * 64 + 32 + lane];
    float2 f0 = __half22float2(a0), f1 = __half22float2(a1);
    float4 acc = make_float4(f0.x * d2, f0.y * d2, f1.x * d2, f1.y * d2);
    int e = d_off[warp], end = d_off[warp + 1];
    int s_next = (e < end) ? d_elist[e] : 0;
    for (; e < end; e++) {
        int s = s_next;
        s_next = (e + 1 < end) ? d_elist[e + 1] : 0;
        float nrm = d_dinv[s] * dv;
        __half2 v0 = Hv[(size_t)s * 64 + lane];
        __half2 v1 = Hv[(size_t)s * 64 + 32 + lane];
        float2 g0 = __half22float2(v0), g1 = __half22float2(v1);
        acc.x += g0.x * nrm; acc.y += g0.y * nrm;
        acc.z += g1.x * nrm; acc.w += g1.y * nrm;
    }
    float* outp = d_aggx + (size_t)warp * IN_DIM;
    *(float2*)(outp + 2 * lane)      = make_float2(acc.x, acc.y);
    *(float2*)(outp + 64 + 2 * lane) = make_float2(acc.z, acc.w);
}

// ---------------- gather 2: grid-stride warps, +bias+relu, fused colsum ----------------
__global__ void k_gather2(const float* __restrict__ bias, int n) {
    int lane = threadIdx.x & 31;
    int wid = threadIdx.x >> 5;   // 0..7
    int gwarp = blockIdx.x * 8 + wid;
    int stride = gridDim.x * 8;
    const __half2* Hv = (const __half2*)d_h2;
    float2 b0 = *(const float2*)(bias + 2 * lane);
    float2 b1 = *(const float2*)(bias + 64 + 2 * lane);
    float4 csum = make_float4(0.f, 0.f, 0.f, 0.f);
    for (int v = gwarp; v < n; v += stride) {
        float dv = d_dinv[v];
        float d2 = dv * dv;
        __half2 a0 = Hv[(size_t)v * 64 + lane];
        __half2 a1 = Hv[(size_t)v * 64 + 32 + lane];
        float2 f0 = __half22float2(a0), f1 = __half22float2(a1);
        float4 acc = make_float4(f0.x * d2, f0.y * d2, f1.x * d2, f1.y * d2);
        int e = d_off[v], end = d_off[v + 1];
        int s_next = (e < end) ? d_elist[e] : 0;
        for (; e < end; e++) {
            int s = s_next;
            s_next = (e + 1 < end) ? d_elist[e + 1] : 0;
            float nrm = d_dinv[s] * dv;
            __half2 v0 = Hv[(size_t)s * 64 + lane];
            __half2 v1 = Hv[(size_t)s * 64 + 32 + lane];
            float2 g0 = __half22float2(v0), g1 = __half22float2(v1);
            acc.x += g0.x * nrm; acc.y += g0.y * nrm;
            acc.z += g1.x * nrm; acc.w += g1.y * nrm;
        }
        acc.x = fmaxf(acc.x + b0.x, 0.f);
        acc.y = fmaxf(acc.y + b0.y, 0.f);
        acc.z = fmaxf(acc.z + b1.x, 0.f);
        acc.w = fmaxf(acc.w + b1.y, 0.f);
        float* outp = d_agg2 + (size_t)v * EMB;
        *(float2*)(outp + 2 * lane)      = make_float2(acc.x, acc.y);
        *(float2*)(outp + 64 + 2 * lane) = make_float2(acc.z, acc.w);
        csum.x += acc.x; csum.y += acc.y; csum.z += acc.z; csum.w += acc.w;
    }
    __shared__ float4 sm[256];
    sm[threadIdx.x] = csum;
    __syncthreads();
    if (wid == 0) {
        float4 s = sm[lane];
        #pragma unroll
        for (int i = 1; i < 8; i++) {
            float4 o = sm[i * 32 + lane];
            s.x += o.x; s.y += o.y; s.z += o.z; s.w += o.w;
        }
        atomicAdd(&d_gsum[2 * lane],     s.x);
        atomicAdd(&d_gsum[2 * lane + 1], s.y);
        atomicAdd(&d_gsum[64 + 2 * lane],     s.z);
        atomicAdd(&d_gsum[64 + 2 * lane + 1], s.w);
    }
}

// ---------------- tf32 tensor-core GEMM: 128x128 tile, BK=32, 256 threads ----
// MODE 0: C = relu(acc + bias) fp32; MODE 1: C = acc written as fp16
#define APAD 36
#define BPAD 136
template <int MODE>
__global__ __launch_bounds__(256, 2)
void tgemm128(int M, int N, int K,
              const float* __restrict__ A, const float* __restrict__ B,
              const float* __restrict__ bias, void* __restrict__ Cout) {
    __shared__ uint32_t As[128][APAD];
    __shared__ uint32_t Bs[32][BPAD];

    int t = threadIdx.x;
    int lane = t & 31;
    int warp = t >> 5;
    int wr = warp >> 2;
    int wc = warp & 3;
    int row0 = blockIdx.y * 128, col0 = blockIdx.x * 128;

    float acc[4][4][4];
    #pragma unroll
    for (int i = 0; i < 4; i++)
        #pragma unroll
        for (int j = 0; j < 4; j++)
            #pragma unroll
            for (int r = 0; r < 4; r++) acc[i][j][r] = 0.f;

    int arow = t >> 1;
    int acb = (t & 1) * 16;
    int brow = t >> 3;
    int bcb = (t & 7) * 16;

    for (int k0 = 0; k0 < K; k0 += 32) {
        {
            int gr = row0 + arow;
            const float* ap = A + (size_t)gr * K + k0 + acb;
            #pragma unroll
            for (int i = 0; i < 4; i++) {
                float4 v = make_float4(0.f, 0.f, 0.f, 0.f);
                if (gr < M) v = *(const float4*)(ap + i * 4);
                uint4 u;
                u.x = f2tf32(v.x); u.y = f2tf32(v.y);
                u.z = f2tf32(v.z); u.w = f2tf32(v.w);
                *(uint4*)&As[arow][acb + i * 4] = u;
            }
        }
        {
            const float* bp = B + (size_t)(k0 + brow) * N + col0 + bcb;
            #pragma unroll
            for (int i = 0; i < 4; i++) {
                float4 v = *(const float4*)(bp + i * 4);
                uint4 u;
                u.x = f2tf32(v.x); u.y = f2tf32(v.y);
                u.z = f2tf32(v.z); u.w = f2tf32(v.w);
                *(uint4*)&Bs[brow][bcb + i * 4] = u;
            }
        }
        __syncthreads();

        #pragma unroll
        for (int ks = 0; ks < 4; ks++) {
            int kk = ks * 8;
            uint32_t af[4][4];
            #pragma unroll
            for (int mi = 0; mi < 4; mi++) {
                int mr = wr * 64 + mi * 16 + (lane >> 2);
                int kc = kk + (lane & 3);
                af[mi][0] = As[mr][kc];
                af[mi][1] = As[mr + 8][kc];
                af[mi][2] = As[mr][kc + 4];
                af[mi][3] = As[mr + 8][kc + 4];
            }
            uint32_t bf[4][2];
            #pragma unroll
            for (int nj = 0; nj < 4; nj++) {
                int bc = wc * 32 + nj * 8 + (lane >> 2);
                int kr = kk + (lane & 3);
                bf[nj][0] = Bs[kr][bc];
                bf[nj][1] = Bs[kr + 4][bc];
            }
            #pragma unroll
            for (int mi = 0; mi < 4; mi++)
                #pragma unroll
                for (int nj = 0; nj < 4; nj++) {
                    asm volatile(
                        "mma.sync.aligned.m16n8k8.row.col.f32.tf32.tf32.f32 "
                        "{%0,%1,%2,%3}, {%4,%5,%6,%7}, {%8,%9}, {%0,%1,%2,%3};"
                        : "+f"(acc[mi][nj][0]), "+f"(acc[mi][nj][1]),
                          "+f"(acc[mi][nj][2]), "+f"(acc[mi][nj][3])
                        : "r"(af[mi][0]), "r"(af[mi][1]), "r"(af[mi][2]), "r"(af[mi][3]),
                          "r"(bf[nj][0]), "r"(bf[nj][1]));
                }
        }
        __syncthreads();
    }

    #pragma unroll
    for (int mi = 0; mi < 4; mi++) {
        int r_lo = row0 + wr * 64 + mi * 16 + (lane >> 2);
        int r_hi = r_lo + 8;
        #pragma unroll
        for (int nj = 0; nj < 4; nj++) {
            int c = col0 + wc * 32 + nj * 8 + (lane & 3) * 2;
            if (MODE == 0) {
                float b0 = bias[c], b1 = bias[c + 1];
                float* C = (float*)Cout;
                float2 lo, hi;
                lo.x = fmaxf(acc[mi][nj][0] + b0, 0.f);
                lo.y = fmaxf(acc[mi][nj][1] + b1, 0.f);
                hi.x = fmaxf(acc[mi][nj][2] + b0, 0.f);
                hi.y = fmaxf(acc[mi][nj][3] + b1, 0.f);
                if (r_lo < M) *(float2*)(C + (size_t)r_lo * N + c) = lo;
                if (r_hi < M) *(float2*)(C + (size_t)r_hi * N + c) = hi;
            } else {
                __half* C = (__half*)Cout;
                if (r_lo < M)
                    *(__half2*)(C + (size_t)r_lo * N + c) =
                        __floats2half2_rn(acc[mi][nj][0], acc[mi][nj][1]);
                if (r_hi < M)
                    *(__half2*)(C + (size_t)r_hi * N + c) =
                        __floats2half2_rn(acc[mi][nj][2], acc[mi][nj][3]);
            }
        }
    }
}

// ---------------- global heads ----------------
__global__ void k_head(const float* __restrict__ fc1W, const float* __restrict__ fc1b,
                       const float* __restrict__ fc2W, const float* __restrict__ fc2b,
                       const float* __restrict__ gpW, const float* __restrict__ gpb,
                       float* __restrict__ out_global, float* __restrict__ out_value,
                       float invN) {
    __shared__ float g[EMB];
    __shared__ float red[256];
    int t = threadIdx.x;
    if (t < EMB) g[t] = d_gsum[t] * invN;
    __syncthreads();
    float acc = fc1b[t];
    #pragma unroll 4
    for (int k = 0; k < EMB; k++) acc += g[k] * fc1W[k * HID + t];
    float v = fmaxf(acc, 0.f);
    red[t] = v * fc2W[t];
    __syncthreads();
    for (int o = 128; o; o >>= 1) {
        if (t < o) red[t] += red[t + o];
        __syncthreads();
    }
    if (t == 0) out_value[0] = red[0] + fc2b[0];
    __syncthreads();
    red[t] = (t < EMB) ? g[t] * gpW[t] : 0.f;
    __syncthreads();
    for (int o = 128; o; o >>= 1) {
        if (t < o) red[t] += red[t + o];
        __syncthreads();
    }
    if (t == 0) out_global[0] = red[0] + gpb[0];
}

// ---------------- per-node heads: node logits + edge projections ----------------
__global__ void k_pernode(const float* __restrict__ H,
                          const float* __restrict__ npW, const float* __restrict__ npb,
                          const float* __restrict__ epW,
                          float* __restrict__ out_node, int n) {
    __shared__ float sNp[EMB * 3];
    __shared__ float sEu[EMB * 2];
    __shared__ float sEv[EMB * 2];
    for (int i = threadIdx.x; i < EMB * 3; i += blockDim.x) sNp[i] = npW[i];
    for (int i = threadIdx.x; i < EMB * 2; i += blockDim.x) sEu[i] = epW[i];
    for (int i = threadIdx.x; i < EMB * 2; i += blockDim.x) sEv[i] = epW[EMB * 2 + i];
    __syncthreads();

    int warp = (blockIdx.x * blockDim.x + threadIdx.x) >> 5;
    int lane = threadIdx.x & 31;
    if (warp >= n) return;
    float4 h = ((const float4*)(H + (size_t)warp * EMB))[lane];
    float hv[4] = {h.x, h.y, h.z, h.w};
    int k = lane * 4;
    float np0 = 0.f, np1 = 0.f, np2 = 0.f;
    float pu0 = 0.f, pu1 = 0.f, pv0 = 0.f, pv1 = 0.f;
    #pragma unroll
    for (int j = 0; j < 4; j++) {
        float x = hv[j];
        np0 += x * sNp[(k + j) * 3 + 0];
        np1 += x * sNp[(k + j) * 3 + 1];
        np2 += x * sNp[(k + j) * 3 + 2];
        pu0 += x * sEu[(k + j) * 2 + 0];
        pu1 += x * sEu[(k + j) * 2 + 1];
        pv0 += x * sEv[(k + j) * 2 + 0];
        pv1 += x * sEv[(k + j) * 2 + 1];
    }
    np0 = warp_sum(np0); np1 = warp_sum(np1); np2 = warp_sum(np2);
    pu0 = warp_sum(pu0); pu1 = warp_sum(pu1);
    pv0 = warp_sum(pv0); pv1 = warp_sum(pv1);
    if (lane == 0) {
        out_node[(size_t)warp * 3 + 0] = np0 + npb[0];
        out_node[(size_t)warp * 3 + 1] = np1 + npb[1];
        out_node[(size_t)warp * 3 + 2] = np2 + npb[2];
        d_pnode[warp] = make_float4(pu0, pu1, pv0, pv1);
    }
}

// ---------------- edge logits ----------------
__global__ void k_edge(const int* __restrict__ src, const int* __restrict__ dst,
                       const float* __restrict__ epb, float* __restrict__ out, int E) {
    int i = blockIdx.x * blockDim.x + threadIdx.x;
    if (i >= E) return;
    int s = src[i], d = dst[i];
    float4 ps = d_pnode[s];
    float4 pd = d_pnode[d];
    float2 o;
    o.x = ps.x + pd.z + epb[0];
    o.y = ps.y + pd.w + epb[1];
    *(float2*)(out + (size_t)i * 2) = o;
}

// ---------------- launch ----------------
extern "C" void kernel_launch(void* const* d_in, const int* in_sizes, int n_in,
                              void* d_out, int out_size) {
    const float* x     = (const float*)d_in[0];
    const int*   ei    = (const int*)d_in[1];
    const float* W1    = (const float*)d_in[2];
    const float* b1    = (const float*)d_in[3];
    const float* W2    = (const float*)d_in[4];
    const float* b2    = (const float*)d_in[5];
    const float* fc1W  = (const float*)d_in[6];
    const float* fc1b  = (const float*)d_in[7];
    const float* fc2W  = (const float*)d_in[8];
    const float* fc2b  = (const float*)d_in[9];
    const float* npW   = (const float*)d_in[10];
    const float* npb   = (const float*)d_in[11];
    const float* epW   = (const float*)d_in[12];
    const float* epb   = (const float*)d_in[13];
    const float* gpW   = (const float*)d_in[14];
    const float* gpb   = (const float*)d_in[15];

    int n = in_sizes[0] / IN_DIM;   // 50000
    int E = in_sizes[1] / 2;        // 800000
    const int* src = ei;
    const int* dst = ei + E;

    float* out = (float*)d_out;
    float* out_node   = out;
    float* out_edge   = out + (size_t)n * 3;
    float* out_global = out + (size_t)n * 3 + (size_t)E * 2;
    float* out_value  = out_global + 1;

    float *aggx, *h1, *agg2;
    void *h2;
    cudaGetSymbolAddress((void**)&aggx, d_aggx);
    cudaGetSymbolAddress((void**)&h1, d_h1);
    cudaGetSymbolAddress(&h2, d_h2);
    cudaGetSymbolAddress((void**)&agg2, d_agg2);

    // CSR build + x fp16 convert
    k_prep<<<((size_t)n * (IN_DIM / 2) + 255) / 256, 256>>>(x, n);
    k_deg<<<(E + 255) / 256, 256>>>(dst, E);
    k_scan<<<1, 1024>>>(n, E, (n + 1023) / 1024);
    k_fill<<<(E + 255) / 256, 256>>>(src, dst, E);

    // Layer 1: gather x (fp16 in), tf32 GEMM (+bias+relu)
    k_gather1<<<(n + 7) / 8, 256>>>(n);
    {
        dim3 grid(HID / 128, (n + 127) / 128);
        tgemm128<0><<<grid, 256>>>(n, HID, IN_DIM, aggx, W1, b1, (void*)h1);
    }
    // Layer 2: tf32 GEMM -> fp16 h2, gather (+bias+relu+colsum)
    {
        dim3 grid(EMB / 128, (n + 127) / 128);
        tgemm128<1><<<grid, 256>>>(n, EMB, HID, h1, W2, nullptr, h2);
    }
    k_gather2<<<256, 256>>>(b2, n);

    // Heads
    k_head<<<1, 256>>>(fc1W, fc1b, fc2W, fc2b, gpW, gpb, out_global, out_value, 1.0f / (float)n);
    k_pernode<<<(n + 7) / 8, 256>>>(agg2, npW, npb, epW, out_node, n);
    k_edge<<<(E + 255) / 256, 256>>>(src, dst, epb, out_edge, E);
}

// round 6
// speedup vs baseline: 1.6281x; 1.6281x over previous
#include <cuda_runtime.h>
#include <cuda_fp16.h>
#include <math.h>
#include <stdint.h>

#define IN_DIM 128
#define HID 256
#define EMB 128
#define MAXN 50000
#define MAXE 800000
#define SCAN_BS 256

// ---------------- scratch (device globals; no allocation) ----------------
__device__ int    d_degi[MAXN];
__device__ float  d_dinv[MAXN];
__device__ int    d_off[MAXN + 1];
__device__ int    d_cursor[MAXN];
__device__ int    d_partial[(MAXN + SCAN_BS - 1) / SCAN_BS + 1];
__device__ int    d_elist[MAXE];
__device__ __half d_xh[MAXN * IN_DIM];    // x in fp16
__device__ float  d_aggx[MAXN * IN_DIM];  // aggregated x (fp32)
__device__ float  d_h1[MAXN * HID];       // relu(aggx@W1+b1)
__device__ __half d_h2[MAXN * EMB];       // h1@W2 in fp16
__device__ float  d_agg2[MAXN * EMB];     // final H (fp32)
__device__ float  d_gsum[EMB];
__device__ float4 d_pnode[MAXN];

__device__ __forceinline__ float warp_sum(float v) {
    #pragma unroll
    for (int o = 16; o; o >>= 1) v += __shfl_down_sync(0xffffffffu, v, o);
    return v;
}

__device__ __forceinline__ uint32_t f2tf32(float f) {
    uint32_t r;
    asm("cvt.rna.tf32.f32 %0, %1;" : "=r"(r) : "f"(f));
    return r;
}

// unpack uint2 (4 halves) -> 4 floats
__device__ __forceinline__ float4 h4_to_f4(uint2 u) {
    __half2 h0 = *(__half2*)&u.x;
    __half2 h1 = *(__half2*)&u.y;
    float2 f0 = __half22float2(h0);
    float2 f1 = __half22float2(h1);
    return make_float4(f0.x, f0.y, f1.x, f1.y);
}

// ---------------- prep: zero deg/gsum + convert x -> fp16 ----------------
__global__ void k_prep(const float* __restrict__ x, int n) {
    int i = blockIdx.x * blockDim.x + threadIdx.x;
    int total = n * (IN_DIM / 2);
    if (i < total) {
        float2 v = ((const float2*)x)[i];
        ((__half2*)d_xh)[i] = __floats2half2_rn(v.x, v.y);
    }
    if (i < n) d_degi[i] = 0;
    if (i < EMB) d_gsum[i] = 0.f;
}

__global__ void k_deg(const int* __restrict__ dst, int E) {
    int i = blockIdx.x * blockDim.x + threadIdx.x;
    if (i < E) atomicAdd(&d_degi[dst[i]], 1);
}

__global__ void k_dinv(int n) {
    int i = blockIdx.x * blockDim.x + threadIdx.x;
    if (i < n) d_dinv[i] = rsqrtf((float)d_degi[i] + 1.0f);
}

// ---------------- 3-kernel exclusive scan ----------------
__global__ void k_scan1(int n) {
    __shared__ int sm[SCAN_BS];
    int t = threadIdx.x;
    int i = blockIdx.x * SCAN_BS + t;
    int v = (i < n) ? d_degi[i] : 0;
    sm[t] = v;
    __syncthreads();
    #pragma unroll
    for (int o = 1; o < SCAN_BS; o <<= 1) {
        int add = (t >= o) ? sm[t - o] : 0;
        __syncthreads();
        sm[t] += add;
        __syncthreads();
    }
    if (i < n) d_off[i] = sm[t] - v;
    if (t == SCAN_BS - 1) d_partial[blockIdx.x] = sm[t];
}

__global__ void k_scan2(int nblk) {
    __shared__ int sm[SCAN_BS];
    int t = threadIdx.x;
    int v = (t < nblk) ? d_partial[t] : 0;
    sm[t] = v;
    __syncthreads();
    #pragma unroll
    for (int o = 1; o < SCAN_BS; o <<= 1) {
        int add = (t >= o) ? sm[t - o] : 0;
        __syncthreads();
        sm[t] += add;
        __syncthreads();
    }
    if (t < nblk) d_partial[t] = sm[t] - v;
}

__global__ void k_scan3(int n, int E) {
    int i = blockIdx.x * blockDim.x + threadIdx.x;
    if (i < n) {
        int o = d_off[i] + d_partial[i / SCAN_BS];
        d_off[i] = o;
        d_cursor[i] = o;
    }
    if (i == 0) d_off[n] = E;
}

__global__ void k_fill(const int* __restrict__ src, const int* __restrict__ dst, int E) {
    int i = blockIdx.x * blockDim.x + threadIdx.x;
    if (i >= E) return;
    int d = dst[i];
    int pos = atomicAdd(&d_cursor[d], 1);
    d_elist[pos] = src[i];
}

// ---------------- gather: warp per node, fp16 in (uint2/lane), fp32 out ----------------
// IN rows have NCOL halves (NCOL/4 uint2 per row; lane covers cols [4*lane,4*lane+4))
// RELU: +bias then relu on output.
template <int NCOL, bool RELU>
__global__ void k_gather(const __half* __restrict__ Hh, float* __restrict__ OUT,
                         const float* __restrict__ bias, int n) {
    int warp = (blockIdx.x * blockDim.x + threadIdx.x) >> 5;
    int lane = threadIdx.x & 31;
    if (warp >= n) return;
    float dv = d_dinv[warp];
    float d2 = dv * dv;
    const uint2* Hv = (const uint2*)Hh;
    float4 h = h4_to_f4(Hv[(size_t)warp * (NCOL / 4) + lane]);
    float4 acc = make_float4(h.x * d2, h.y * d2, h.z * d2, h.w * d2);
    int e = d_off[warp], end = d_off[warp + 1];
    int s_next = (e < end) ? d_elist[e] : 0;
    for (; e < end; e++) {
        int s = s_next;
        s_next = (e + 1 < end) ? d_elist[e + 1] : 0;
        float nrm = d_dinv[s] * dv;
        float4 v = h4_to_f4(Hv[(size_t)s * (NCOL / 4) + lane]);
        acc.x += v.x * nrm; acc.y += v.y * nrm;
        acc.z += v.z * nrm; acc.w += v.w * nrm;
    }
    if (RELU) {
        float4 b = ((const float4*)bias)[lane];
        acc.x = fmaxf(acc.x + b.x, 0.f);
        acc.y = fmaxf(acc.y + b.y, 0.f);
        acc.z = fmaxf(acc.z + b.z, 0.f);
        acc.w = fmaxf(acc.w + b.w, 0.f);
    }
    ((float4*)OUT)[(size_t)warp * (NCOL / 4) + lane] = acc;
}

// ---------------- tf32 tensor-core GEMM: 128x128 tile, BK=32, 256 threads ----
// MODE 0: C = relu(acc + bias) fp32; MODE 1: C = acc written as fp16
#define APAD 36
#define BPAD 136
template <int MODE>
__global__ __launch_bounds__(256, 2)
void tgemm128(int M, int N, int K,
              const float* __restrict__ A, const float* __restrict__ B,
              const float* __restrict__ bias, void* __restrict__ Cout) {
    __shared__ uint32_t As[128][APAD];
    __shared__ uint32_t Bs[32][BPAD];

    int t = threadIdx.x;
    int lane = t & 31;
    int warp = t >> 5;
    int wr = warp >> 2;
    int wc = warp & 3;
    int row0 = blockIdx.y * 128, col0 = blockIdx.x * 128;

    float acc[4][4][4];
    #pragma unroll
    for (int i = 0; i < 4; i++)
        #pragma unroll
        for (int j = 0; j < 4; j++)
            #pragma unroll
            for (int r = 0; r < 4; r++) acc[i][j][r] = 0.f;

    int arow = t >> 1;
    int acb = (t & 1) * 16;
    int brow = t >> 3;
    int bcb = (t & 7) * 16;

    for (int k0 = 0; k0 < K; k0 += 32) {
        {
            int gr = row0 + arow;
            const float* ap = A + (size_t)gr * K + k0 + acb;
            #pragma unroll
            for (int i = 0; i < 4; i++) {
                float4 v = make_float4(0.f, 0.f, 0.f, 0.f);
                if (gr < M) v = *(const float4*)(ap + i * 4);
                uint4 u;
                u.x = f2tf32(v.x); u.y = f2tf32(v.y);
                u.z = f2tf32(v.z); u.w = f2tf32(v.w);
                *(uint4*)&As[arow][acb + i * 4] = u;
            }
        }
        {
            const float* bp = B + (size_t)(k0 + brow) * N + col0 + bcb;
            #pragma unroll
            for (int i = 0; i < 4; i++) {
                float4 v = *(const float4*)(bp + i * 4);
                uint4 u;
                u.x = f2tf32(v.x); u.y = f2tf32(v.y);
                u.z = f2tf32(v.z); u.w = f2tf32(v.w);
                *(uint4*)&Bs[brow][bcb + i * 4] = u;
            }
        }
        __syncthreads();

        #pragma unroll
        for (int ks = 0; ks < 4; ks++) {
            int kk = ks * 8;
            uint32_t af[4][4];
            #pragma unroll
            for (int mi = 0; mi < 4; mi++) {
                int mr = wr * 64 + mi * 16 + (lane >> 2);
                int kc = kk + (lane & 3);
                af[mi][0] = As[mr][kc];
                af[mi][1] = As[mr + 8][kc];
                af[mi][2] = As[mr][kc + 4];
                af[mi][3] = As[mr + 8][kc + 4];
            }
            uint32_t bf[4][2];
            #pragma unroll
            for (int nj = 0; nj < 4; nj++) {
                int bc = wc * 32 + nj * 8 + (lane >> 2);
                int kr = kk + (lane & 3);
                bf[nj][0] = Bs[kr][bc];
                bf[nj][1] = Bs[kr + 4][bc];
            }
            #pragma unroll
            for (int mi = 0; mi < 4; mi++)
                #pragma unroll
                for (int nj = 0; nj < 4; nj++) {
                    asm volatile(
                        "mma.sync.aligned.m16n8k8.row.col.f32.tf32.tf32.f32 "
                        "{%0,%1,%2,%3}, {%4,%5,%6,%7}, {%8,%9}, {%0,%1,%2,%3};"
                        : "+f"(acc[mi][nj][0]), "+f"(acc[mi][nj][1]),
                          "+f"(acc[mi][nj][2]), "+f"(acc[mi][nj][3])
                        : "r"(af[mi][0]), "r"(af[mi][1]), "r"(af[mi][2]), "r"(af[mi][3]),
                          "r"(bf[nj][0]), "r"(bf[nj][1]));
                }
        }
        __syncthreads();
    }

    #pragma unroll
    for (int mi = 0; mi < 4; mi++) {
        int r_lo = row0 + wr * 64 + mi * 16 + (lane >> 2);
        int r_hi = r_lo + 8;
        #pragma unroll
        for (int nj = 0; nj < 4; nj++) {
            int c = col0 + wc * 32 + nj * 8 + (lane & 3) * 2;
            if (MODE == 0) {
                float b0 = bias[c], b1 = bias[c + 1];
                float* C = (float*)Cout;
                float2 lo, hi;
                lo.x = fmaxf(acc[mi][nj][0] + b0, 0.f);
                lo.y = fmaxf(acc[mi][nj][1] + b1, 0.f);
                hi.x = fmaxf(acc[mi][nj][2] + b0, 0.f);
                hi.y = fmaxf(acc[mi][nj][3] + b1, 0.f);
                if (r_lo < M) *(float2*)(C + (size_t)r_lo * N + c) = lo;
                if (r_hi < M) *(float2*)(C + (size_t)r_hi * N + c) = hi;
            } else {
                __half* C = (__half*)Cout;
                if (r_lo < M)
                    *(__half2*)(C + (size_t)r_lo * N + c) =
                        __floats2half2_rn(acc[mi][nj][0], acc[mi][nj][1]);
                if (r_hi < M)
                    *(__half2*)(C + (size_t)r_hi * N + c) =
                        __floats2half2_rn(acc[mi][nj][2], acc[mi][nj][3]);
            }
        }
    }
}

// ---------------- column sums of H (read-only) ----------------
__global__ void k_colmean(const float* __restrict__ H, int n) {
    int c4 = threadIdx.x & 31;
    int ry = threadIdx.x >> 5;
    float4 sum = make_float4(0.f, 0.f, 0.f, 0.f);
    for (int row = blockIdx.x * 8 + ry; row < n; row += gridDim.x * 8) {
        float4 a = ((const float4*)H)[(size_t)row * 32 + c4];
        sum.x += a.x; sum.y += a.y; sum.z += a.z; sum.w += a.w;
    }
    __shared__ float4 sm[256];
    sm[threadIdx.x] = sum;
    __syncthreads();
    if (ry == 0) {
        #pragma unroll
        for (int i = 1; i < 8; i++) {
            float4 o = sm[i * 32 + c4];
            sum.x += o.x; sum.y += o.y; sum.z += o.z; sum.w += o.w;
        }
        atomicAdd(&d_gsum[c4 * 4 + 0], sum.x);
        atomicAdd(&d_gsum[c4 * 4 + 1], sum.y);
        atomicAdd(&d_gsum[c4 * 4 + 2], sum.z);
        atomicAdd(&d_gsum[c4 * 4 + 3], sum.w);
    }
}

// ---------------- global heads ----------------
__global__ void k_head(const float* __restrict__ fc1W, const float* __restrict__ fc1b,
                       const float* __restrict__ fc2W, const float* __restrict__ fc2b,
                       const float* __restrict__ gpW, const float* __restrict__ gpb,
                       float* __restrict__ out_global, float* __restrict__ out_value,
                       float invN) {
    __shared__ float g[EMB];
    __shared__ float red[256];
    int t = threadIdx.x;
    if (t < EMB) g[t] = d_gsum[t] * invN;
    __syncthreads();
    float acc = fc1b[t];
    #pragma unroll 4
    for (int k = 0; k < EMB; k++) acc += g[k] * fc1W[k * HID + t];
    float v = fmaxf(acc, 0.f);
    red[t] = v * fc2W[t];
    __syncthreads();
    for (int o = 128; o; o >>= 1) {
        if (t < o) red[t] += red[t + o];
        __syncthreads();
    }
    if (t == 0) out_value[0] = red[0] + fc2b[0];
    __syncthreads();
    red[t] = (t < EMB) ? g[t] * gpW[t] : 0.f;
    __syncthreads();
    for (int o = 128; o; o >>= 1) {
        if (t < o) red[t] += red[t + o];
        __syncthreads();
    }
    if (t == 0) out_global[0] = red[0] + gpb[0];
}

// ---------------- per-node heads: node logits + edge projections ----------------
__global__ void k_pernode(const float* __restrict__ H,
                          const float* __restrict__ npW, const float* __restrict__ npb,
                          const float* __restrict__ epW,
                          float* __restrict__ out_node, int n) {
    __shared__ float sNp[EMB * 3];
    __shared__ float sEu[EMB * 2];
    __shared__ float sEv[EMB * 2];
    for (int i = threadIdx.x; i < EMB * 3; i += blockDim.x) sNp[i] = npW[i];
    for (int i = threadIdx.x; i < EMB * 2; i += blockDim.x) sEu[i] = epW[i];
    for (int i = threadIdx.x; i < EMB * 2; i += blockDim.x) sEv[i] = epW[EMB * 2 + i];
    __syncthreads();

    int warp = (blockIdx.x * blockDim.x + threadIdx.x) >> 5;
    int lane = threadIdx.x & 31;
    if (warp >= n) return;
    float4 h = ((const float4*)(H + (size_t)warp * EMB))[lane];
    float hv[4] = {h.x, h.y, h.z, h.w};
    int k = lane * 4;
    float np0 = 0.f, np1 = 0.f, np2 = 0.f;
    float pu0 = 0.f, pu1 = 0.f, pv0 = 0.f, pv1 = 0.f;
    #pragma unroll
    for (int j = 0; j < 4; j++) {
        float x = hv[j];
        np0 += x * sNp[(k + j) * 3 + 0];
        np1 += x * sNp[(k + j) * 3 + 1];
        np2 += x * sNp[(k + j) * 3 + 2];
        pu0 += x * sEu[(k + j) * 2 + 0];
        pu1 += x * sEu[(k + j) * 2 + 1];
        pv0 += x * sEv[(k + j) * 2 + 0];
        pv1 += x * sEv[(k + j) * 2 + 1];
    }
    np0 = warp_sum(np0); np1 = warp_sum(np1); np2 = warp_sum(np2);
    pu0 = warp_sum(pu0); pu1 = warp_sum(pu1);
    pv0 = warp_sum(pv0); pv1 = warp_sum(pv1);
    if (lane == 0) {
        out_node[(size_t)warp * 3 + 0] = np0 + npb[0];
        out_node[(size_t)warp * 3 + 1] = np1 + npb[1];
        out_node[(size_t)warp * 3 + 2] = np2 + npb[2];
        d_pnode[warp] = make_float4(pu0, pu1, pv0, pv1);
    }
}

// ---------------- edge logits ----------------
__global__ void k_edge(const int* __restrict__ src, const int* __restrict__ dst,
                       const float* __restrict__ epb, float* __restrict__ out, int E) {
    int i = blockIdx.x * blockDim.x + threadIdx.x;
    if (i >= E) return;
    int s = src[i], d = dst[i];
    float4 ps = d_pnode[s];
    float4 pd = d_pnode[d];
    float2 o;
    o.x = ps.x + pd.z + epb[0];
    o.y = ps.y + pd.w + epb[1];
    *(float2*)(out + (size_t)i * 2) = o;
}

// ---------------- launch ----------------
extern "C" void kernel_launch(void* const* d_in, const int* in_sizes, int n_in,
                              void* d_out, int out_size) {
    const float* x     = (const float*)d_in[0];
    const int*   ei    = (const int*)d_in[1];
    const float* W1    = (const float*)d_in[2];
    const float* b1    = (const float*)d_in[3];
    const float* W2    = (const float*)d_in[4];
    const float* b2    = (const float*)d_in[5];
    const float* fc1W  = (const float*)d_in[6];
    const float* fc1b  = (const float*)d_in[7];
    const float* fc2W  = (const float*)d_in[8];
    const float* fc2b  = (const float*)d_in[9];
    const float* npW   = (const float*)d_in[10];
    const float* npb   = (const float*)d_in[11];
    const float* epW   = (const float*)d_in[12];
    const float* epb   = (const float*)d_in[13];
    const float* gpW   = (const float*)d_in[14];
    const float* gpb   = (const float*)d_in[15];

    int n = in_sizes[0] / IN_DIM;   // 50000
    int E = in_sizes[1] / 2;        // 800000
    const int* src = ei;
    const int* dst = ei + E;

    float* out = (float*)d_out;
    float* out_node   = out;
    float* out_edge   = out + (size_t)n * 3;
    float* out_global = out + (size_t)n * 3 + (size_t)E * 2;
    float* out_value  = out_global + 1;

    float *aggx, *h1, *agg2;
    __half *xh, *h2;
    cudaGetSymbolAddress((void**)&aggx, d_aggx);
    cudaGetSymbolAddress((void**)&h1, d_h1);
    cudaGetSymbolAddress((void**)&agg2, d_agg2);
    cudaGetSymbolAddress((void**)&xh, d_xh);
    cudaGetSymbolAddress((void**)&h2, d_h2);

    int nblk = (n + SCAN_BS - 1) / SCAN_BS;

    // CSR build + x fp16 convert
    k_prep<<<((size_t)n * (IN_DIM / 2) + 255) / 256, 256>>>(x, n);
    k_deg<<<(E + 255) / 256, 256>>>(dst, E);
    k_dinv<<<(n + 255) / 256, 256>>>(n);
    k_scan1<<<nblk, SCAN_BS>>>(n);
    k_scan2<<<1, SCAN_BS>>>(nblk);
    k_scan3<<<(n + 255) / 256, 256>>>(n, E);
    k_fill<<<(E + 255) / 256, 256>>>(src, dst, E);

    // Layer 1: gather x (fp16 in), tf32 GEMM (+bias+relu)
    k_gather<IN_DIM, false><<<(n + 7) / 8, 256>>>(xh, aggx, nullptr, n);
    {
        dim3 grid(HID / 128, (n + 127) / 128);
        tgemm128<0><<<grid, 256>>>(n, HID, IN_DIM, aggx, W1, b1, (void*)h1);
    }
    // Layer 2: tf32 GEMM -> fp16 h2, gather (+bias+relu)
    {
        dim3 grid(EMB / 128, (n + 127) / 128);
        tgemm128<1><<<grid, 256>>>(n, EMB, HID, h1, W2, nullptr, (void*)h2);
    }
    k_gather<EMB, true><<<(n + 7) / 8, 256>>>(h2, agg2, b2, n);

    // Heads
    k_colmean<<<256, 256>>>(agg2, n);
    k_head<<<1, 256>>>(fc1W, fc1b, fc2W, fc2b, gpW, gpb, out_global, out_value, 1.0f / (float)n);
    k_pernode<<<(n + 7) / 8, 256>>>(agg2, npW, npb, epW, out_node, n);
    k_edge<<<(E + 255) / 256, 256>>>(src, dst, epb, out_edge, E);
}

// round 7
// speedup vs baseline: 1.7329x; 1.0643x over previous
#include <cuda_runtime.h>
#include <cuda_fp16.h>
#include <math.h>
#include <stdint.h>

#define IN_DIM 128
#define HID 256
#define EMB 128
#define MAXN 50000
#define MAXE 800000
#define SCAN_BS 256

// ---------------- scratch (device globals; no allocation) ----------------
__device__ int    d_degi[MAXN];
__device__ float  d_dinv[MAXN];
__device__ int    d_off[MAXN + 1];
__device__ int    d_cursor[MAXN];
__device__ int    d_partial[(MAXN + SCAN_BS - 1) / SCAN_BS + 1];
__device__ int    d_elist[MAXE];
__device__ __half d_xh[MAXN * IN_DIM];
__device__ float  d_aggx[MAXN * IN_DIM];
__device__ float  d_h1[MAXN * HID];
__device__ __half d_h2[MAXN * EMB];
__device__ float  d_agg2[MAXN * EMB];
__device__ float  d_gsum[EMB];
__device__ float4 d_pnode[MAXN];

__device__ __forceinline__ float warp_sum(float v) {
    #pragma unroll
    for (int o = 16; o; o >>= 1) v += __shfl_down_sync(0xffffffffu, v, o);
    return v;
}

__device__ __forceinline__ uint32_t f2tf32(float f) {
    uint32_t r;
    asm("cvt.rna.tf32.f32 %0, %1;" : "=r"(r) : "f"(f));
    return r;
}

__device__ __forceinline__ float4 h4_to_f4(uint2 u) {
    __half2 h0 = *(__half2*)&u.x;
    __half2 h1 = *(__half2*)&u.y;
    float2 f0 = __half22float2(h0);
    float2 f1 = __half22float2(h1);
    return make_float4(f0.x, f0.y, f1.x, f1.y);
}

// ---------------- prep: zero deg/gsum + convert x -> fp16 ----------------
__global__ void k_prep(const float* __restrict__ x, int n) {
    int i = blockIdx.x * blockDim.x + threadIdx.x;
    int total = n * (IN_DIM / 2);
    if (i < total) {
        float2 v = ((const float2*)x)[i];
        ((__half2*)d_xh)[i] = __floats2half2_rn(v.x, v.y);
    }
    if (i < n) d_degi[i] = 0;
    if (i < EMB) d_gsum[i] = 0.f;
}

__global__ void k_deg(const int* __restrict__ dst, int E) {
    int i = blockIdx.x * blockDim.x + threadIdx.x;
    if (i < E) atomicAdd(&d_degi[dst[i]], 1);
}

// ---------------- 3-kernel exclusive scan (+dinv fused into scan3) ----------------
__global__ void k_scan1(int n) {
    __shared__ int sm[SCAN_BS];
    int t = threadIdx.x;
    int i = blockIdx.x * SCAN_BS + t;
    int v = (i < n) ? d_degi[i] : 0;
    sm[t] = v;
    __syncthreads();
    #pragma unroll
    for (int o = 1; o < SCAN_BS; o <<= 1) {
        int add = (t >= o) ? sm[t - o] : 0;
        __syncthreads();
        sm[t] += add;
        __syncthreads();
    }
    if (i < n) d_off[i] = sm[t] - v;
    if (t == SCAN_BS - 1) d_partial[blockIdx.x] = sm[t];
}

__global__ void k_scan2(int nblk) {
    __shared__ int sm[SCAN_BS];
    int t = threadIdx.x;
    int v = (t < nblk) ? d_partial[t] : 0;
    sm[t] = v;
    __syncthreads();
    #pragma unroll
    for (int o = 1; o < SCAN_BS; o <<= 1) {
        int add = (t >= o) ? sm[t - o] : 0;
        __syncthreads();
        sm[t] += add;
        __syncthreads();
    }
    if (t < nblk) d_partial[t] = sm[t] - v;
}

__global__ void k_scan3(int n, int E) {
    int i = blockIdx.x * blockDim.x + threadIdx.x;
    if (i < n) {
        int o = d_off[i] + d_partial[i / SCAN_BS];
        d_off[i] = o;
        d_cursor[i] = o;
        d_dinv[i] = rsqrtf((float)d_degi[i] + 1.0f);
    }
    if (i == 0) d_off[n] = E;
}

__global__ void k_fill(const int* __restrict__ src, const int* __restrict__ dst, int E) {
    int i = blockIdx.x * blockDim.x + threadIdx.x;
    if (i >= E) return;
    int d = dst[i];
    int pos = atomicAdd(&d_cursor[d], 1);
    d_elist[pos] = src[i];
}

// ---------------- gather: warp per node, 2-edge unrolled ----------------
template <int NCOL, bool RELU>
__global__ void k_gather(const __half* __restrict__ Hh, float* __restrict__ OUT,
                         const float* __restrict__ bias, int n) {
    int warp = (blockIdx.x * blockDim.x + threadIdx.x) >> 5;
    int lane = threadIdx.x & 31;
    if (warp >= n) return;
    float dv = d_dinv[warp];
    float d2 = dv * dv;
    const uint2* Hv = (const uint2*)Hh;
    float4 h = h4_to_f4(Hv[(size_t)warp * (NCOL / 4) + lane]);
    float4 acc = make_float4(h.x * d2, h.y * d2, h.z * d2, h.w * d2);
    int e = d_off[warp], end = d_off[warp + 1];
    for (; e + 1 < end; e += 2) {
        int s0 = d_elist[e], s1 = d_elist[e + 1];
        float n0 = d_dinv[s0] * dv;
        float n1 = d_dinv[s1] * dv;
        float4 v0 = h4_to_f4(Hv[(size_t)s0 * (NCOL / 4) + lane]);
        float4 v1 = h4_to_f4(Hv[(size_t)s1 * (NCOL / 4) + lane]);
        acc.x += v0.x * n0 + v1.x * n1;
        acc.y += v0.y * n0 + v1.y * n1;
        acc.z += v0.z * n0 + v1.z * n1;
        acc.w += v0.w * n0 + v1.w * n1;
    }
    if (e < end) {
        int s = d_elist[e];
        float nrm = d_dinv[s] * dv;
        float4 v = h4_to_f4(Hv[(size_t)s * (NCOL / 4) + lane]);
        acc.x += v.x * nrm; acc.y += v.y * nrm;
        acc.z += v.z * nrm; acc.w += v.w * nrm;
    }
    if (RELU) {
        float4 b = ((const float4*)bias)[lane];
        acc.x = fmaxf(acc.x + b.x, 0.f);
        acc.y = fmaxf(acc.y + b.y, 0.f);
        acc.z = fmaxf(acc.z + b.z, 0.f);
        acc.w = fmaxf(acc.w + b.w, 0.f);
    }
    ((float4*)OUT)[(size_t)warp * (NCOL / 4) + lane] = acc;
}

// ---------------- tf32 GEMM: 128x128 tile, BK=16, double-buffered ----------------
// MODE 0: C = relu(acc + bias) fp32; MODE 1: C = acc written as fp16
template <int MODE>
__global__ __launch_bounds__(256, 2)
void tgemm128(int M, int N, int K,
              const float* __restrict__ A, const float* __restrict__ B,
              const float* __restrict__ bias, void* __restrict__ Cout) {
    __shared__ uint32_t As[2][128][20];   // [buf][m][k]
    __shared__ uint32_t Bs[2][16][136];   // [buf][k][n]

    int t = threadIdx.x;
    int lane = t & 31;
    int warp = t >> 5;
    int wr = warp >> 2;
    int wc = warp & 3;
    int row0 = blockIdx.y * 128, col0 = blockIdx.x * 128;

    float acc[4][4][4];
    #pragma unroll
    for (int i = 0; i < 4; i++)
        #pragma unroll
        for (int j = 0; j < 4; j++)
            #pragma unroll
            for (int r = 0; r < 4; r++) acc[i][j][r] = 0.f;

    int arow = t >> 1;          // 0..127
    int acb = (t & 1) * 8;      // 0 or 8
    int brow = t >> 4;          // 0..15
    int bcb = (t & 15) * 8;     // 0..120

    int gr = row0 + arow;
    const float* ap = A + (size_t)gr * K + acb;
    const float* bp = B + (size_t)brow * N + col0 + bcb;

    float4 ra0, ra1, rb0, rb1;

    // prologue: load tile 0
    ra0 = make_float4(0.f, 0.f, 0.f, 0.f);
    ra1 = ra0;
    if (gr < M) { ra0 = *(const float4*)(ap); ra1 = *(const float4*)(ap + 4); }
    rb0 = *(const float4*)(bp);
    rb1 = *(const float4*)(bp + 4);
    {
        uint4 u;
        u.x = f2tf32(ra0.x); u.y = f2tf32(ra0.y); u.z = f2tf32(ra0.z); u.w = f2tf32(ra0.w);
        *(uint4*)&As[0][arow][acb] = u;
        u.x = f2tf32(ra1.x); u.y = f2tf32(ra1.y); u.z = f2tf32(ra1.z); u.w = f2tf32(ra1.w);
        *(uint4*)&As[0][arow][acb + 4] = u;
        u.x = f2tf32(rb0.x); u.y = f2tf32(rb0.y); u.z = f2tf32(rb0.z); u.w = f2tf32(rb0.w);
        *(uint4*)&Bs[0][brow][bcb] = u;
        u.x = f2tf32(rb1.x); u.y = f2tf32(rb1.y); u.z = f2tf32(rb1.z); u.w = f2tf32(rb1.w);
        *(uint4*)&Bs[0][brow][bcb + 4] = u;
    }
    __syncthreads();

    int nsteps = K / 16;
    for (int i = 0; i < nsteps; i++) {
        int cur = i & 1, nxt = cur ^ 1;
        bool more = (i + 1 < nsteps);
        if (more) {
            int k0 = (i + 1) * 16;
            ra0 = make_float4(0.f, 0.f, 0.f, 0.f);
            ra1 = ra0;
            if (gr < M) { ra0 = *(const float4*)(ap + k0); ra1 = *(const float4*)(ap + k0 + 4); }
            rb0 = *(const float4*)(bp + (size_t)k0 * N);
            rb1 = *(const float4*)(bp + (size_t)k0 * N + 4);
        }
        // compute current buffer
        #pragma unroll
        for (int ks = 0; ks < 2; ks++) {
            int kk = ks * 8;
            uint32_t af[4][4];
            #pragma unroll
            for (int mi = 0; mi < 4; mi++) {
                int mr = wr * 64 + mi * 16 + (lane >> 2);
                int kc = kk + (lane & 3);
                af[mi][0] = As[cur][mr][kc];
                af[mi][1] = As[cur][mr + 8][kc];
                af[mi][2] = As[cur][mr][kc + 4];
                af[mi][3] = As[cur][mr + 8][kc + 4];
            }
            uint32_t bf[4][2];
            #pragma unroll
            for (int nj = 0; nj < 4; nj++) {
                int bc = wc * 32 + nj * 8 + (lane >> 2);
                int kr = kk + (lane & 3);
                bf[nj][0] = Bs[cur][kr][bc];
                bf[nj][1] = Bs[cur][kr + 4][bc];
            }
            #pragma unroll
            for (int mi = 0; mi < 4; mi++)
                #pragma unroll
                for (int nj = 0; nj < 4; nj++) {
                    asm volatile(
                        "mma.sync.aligned.m16n8k8.row.col.f32.tf32.tf32.f32 "
                        "{%0,%1,%2,%3}, {%4,%5,%6,%7}, {%8,%9}, {%0,%1,%2,%3};"
                        : "+f"(acc[mi][nj][0]), "+f"(acc[mi][nj][1]),
                          "+f"(acc[mi][nj][2]), "+f"(acc[mi][nj][3])
                        : "r"(af[mi][0]), "r"(af[mi][1]), "r"(af[mi][2]), "r"(af[mi][3]),
                          "r"(bf[nj][0]), "r"(bf[nj][1]));
                }
        }
        if (more) {
            uint4 u;
            u.x = f2tf32(ra0.x); u.y = f2tf32(ra0.y); u.z = f2tf32(ra0.z); u.w = f2tf32(ra0.w);
            *(uint4*)&As[nxt][arow][acb] = u;
            u.x = f2tf32(ra1.x); u.y = f2tf32(ra1.y); u.z = f2tf32(ra1.z); u.w = f2tf32(ra1.w);
            *(uint4*)&As[nxt][arow][acb + 4] = u;
            u.x = f2tf32(rb0.x); u.y = f2tf32(rb0.y); u.z = f2tf32(rb0.z); u.w = f2tf32(rb0.w);
            *(uint4*)&Bs[nxt][brow][bcb] = u;
            u.x = f2tf32(rb1.x); u.y = f2tf32(rb1.y); u.z = f2tf32(rb1.z); u.w = f2tf32(rb1.w);
            *(uint4*)&Bs[nxt][brow][bcb + 4] = u;
        }
        __syncthreads();
    }

    #pragma unroll
    for (int mi = 0; mi < 4; mi++) {
        int r_lo = row0 + wr * 64 + mi * 16 + (lane >> 2);
        int r_hi = r_lo + 8;
        #pragma unroll
        for (int nj = 0; nj < 4; nj++) {
            int c = col0 + wc * 32 + nj * 8 + (lane & 3) * 2;
            if (MODE == 0) {
                float b0 = bias[c], b1 = bias[c + 1];
                float* C = (float*)Cout;
                float2 lo, hi;
                lo.x = fmaxf(acc[mi][nj][0] + b0, 0.f);
                lo.y = fmaxf(acc[mi][nj][1] + b1, 0.f);
                hi.x = fmaxf(acc[mi][nj][2] + b0, 0.f);
                hi.y = fmaxf(acc[mi][nj][3] + b1, 0.f);
                if (r_lo < M) *(float2*)(C + (size_t)r_lo * N + c) = lo;
                if (r_hi < M) *(float2*)(C + (size_t)r_hi * N + c) = hi;
            } else {
                __half* C = (__half*)Cout;
                if (r_lo < M)
                    *(__half2*)(C + (size_t)r_lo * N + c) =
                        __floats2half2_rn(acc[mi][nj][0], acc[mi][nj][1]);
                if (r_hi < M)
                    *(__half2*)(C + (size_t)r_hi * N + c) =
                        __floats2half2_rn(acc[mi][nj][2], acc[mi][nj][3]);
            }
        }
    }
}

// ---------------- per-node heads (grid-stride) + fused column sums ----------------
__global__ void k_pernode(const float* __restrict__ H,
                          const float* __restrict__ npW, const float* __restrict__ npb,
                          const float* __restrict__ epW,
                          float* __restrict__ out_node, int n) {
    __shared__ float sNp[EMB * 3];
    __shared__ float sEu[EMB * 2];
    __shared__ float sEv[EMB * 2];
    __shared__ float4 smcol[256];
    for (int i = threadIdx.x; i < EMB * 3; i += blockDim.x) sNp[i] = npW[i];
    for (int i = threadIdx.x; i < EMB * 2; i += blockDim.x) sEu[i] = epW[i];
    for (int i = threadIdx.x; i < EMB * 2; i += blockDim.x) sEv[i] = epW[EMB * 2 + i];
    __syncthreads();

    int lane = threadIdx.x & 31;
    int wid = threadIdx.x >> 5;
    int gwarp = blockIdx.x * 8 + wid;
    int stride = gridDim.x * 8;
    int k = lane * 4;
    float4 csum = make_float4(0.f, 0.f, 0.f, 0.f);

    for (int v = gwarp; v < n; v += stride) {
        float4 h = ((const float4*)(H + (size_t)v * EMB))[lane];
        csum.x += h.x; csum.y += h.y; csum.z += h.z; csum.w += h.w;
        float hv[4] = {h.x, h.y, h.z, h.w};
        float np0 = 0.f, np1 = 0.f, np2 = 0.f;
        float pu0 = 0.f, pu1 = 0.f, pv0 = 0.f, pv1 = 0.f;
        #pragma unroll
        for (int j = 0; j < 4; j++) {
            float xv = hv[j];
            np0 += xv * sNp[(k + j) * 3 + 0];
            np1 += xv * sNp[(k + j) * 3 + 1];
            np2 += xv * sNp[(k + j) * 3 + 2];
            pu0 += xv * sEu[(k + j) * 2 + 0];
            pu1 += xv * sEu[(k + j) * 2 + 1];
            pv0 += xv * sEv[(k + j) * 2 + 0];
            pv1 += xv * sEv[(k + j) * 2 + 1];
        }
        np0 = warp_sum(np0); np1 = warp_sum(np1); np2 = warp_sum(np2);
        pu0 = warp_sum(pu0); pu1 = warp_sum(pu1);
        pv0 = warp_sum(pv0); pv1 = warp_sum(pv1);
        if (lane == 0) {
            out_node[(size_t)v * 3 + 0] = np0 + npb[0];
            out_node[(size_t)v * 3 + 1] = np1 + npb[1];
            out_node[(size_t)v * 3 + 2] = np2 + npb[2];
            d_pnode[v] = make_float4(pu0, pu1, pv0, pv1);
        }
    }
    smcol[threadIdx.x] = csum;
    __syncthreads();
    if (wid == 0) {
        float4 s = smcol[lane];
        #pragma unroll
        for (int i = 1; i < 8; i++) {
            float4 o = smcol[i * 32 + lane];
            s.x += o.x; s.y += o.y; s.z += o.z; s.w += o.w;
        }
        atomicAdd(&d_gsum[4 * lane + 0], s.x);
        atomicAdd(&d_gsum[4 * lane + 1], s.y);
        atomicAdd(&d_gsum[4 * lane + 2], s.z);
        atomicAdd(&d_gsum[4 * lane + 3], s.w);
    }
}

// ---------------- global heads ----------------
__global__ void k_head(const float* __restrict__ fc1W, const float* __restrict__ fc1b,
                       const float* __restrict__ fc2W, const float* __restrict__ fc2b,
                       const float* __restrict__ gpW, const float* __restrict__ gpb,
                       float* __restrict__ out_global, float* __restrict__ out_value,
                       float invN) {
    __shared__ float g[EMB];
    __shared__ float red[256];
    int t = threadIdx.x;
    if (t < EMB) g[t] = d_gsum[t] * invN;
    __syncthreads();
    float acc = fc1b[t];
    #pragma unroll 4
    for (int k = 0; k < EMB; k++) acc += g[k] * fc1W[k * HID + t];
    float v = fmaxf(acc, 0.f);
    red[t] = v * fc2W[t];
    __syncthreads();
    for (int o = 128; o; o >>= 1) {
        if (t < o) red[t] += red[t + o];
        __syncthreads();
    }
    if (t == 0) out_value[0] = red[0] + fc2b[0];
    __syncthreads();
    red[t] = (t < EMB) ? g[t] * gpW[t] : 0.f;
    __syncthreads();
    for (int o = 128; o; o >>= 1) {
        if (t < o) red[t] += red[t + o];
        __syncthreads();
    }
    if (t == 0) out_global[0] = red[0] + gpb[0];
}

// ---------------- edge logits ----------------
__global__ void k_edge(const int* __restrict__ src, const int* __restrict__ dst,
                       const float* __restrict__ epb, float* __restrict__ out, int E) {
    int i = blockIdx.x * blockDim.x + threadIdx.x;
    if (i >= E) return;
    int s = src[i], d = dst[i];
    float4 ps = d_pnode[s];
    float4 pd = d_pnode[d];
    float2 o;
    o.x = ps.x + pd.z + epb[0];
    o.y = ps.y + pd.w + epb[1];
    *(float2*)(out + (size_t)i * 2) = o;
}

// ---------------- launch ----------------
extern "C" void kernel_launch(void* const* d_in, const int* in_sizes, int n_in,
                              void* d_out, int out_size) {
    const float* x     = (const float*)d_in[0];
    const int*   ei    = (const int*)d_in[1];
    const float* W1    = (const float*)d_in[2];
    const float* b1    = (const float*)d_in[3];
    const float* W2    = (const float*)d_in[4];
    const float* b2    = (const float*)d_in[5];
    const float* fc1W  = (const float*)d_in[6];
    const float* fc1b  = (const float*)d_in[7];
    const float* fc2W  = (const float*)d_in[8];
    const float* fc2b  = (const float*)d_in[9];
    const float* npW   = (const float*)d_in[10];
    const float* npb   = (const float*)d_in[11];
    const float* epW   = (const float*)d_in[12];
    const float* epb   = (const float*)d_in[13];
    const float* gpW   = (const float*)d_in[14];
    const float* gpb   = (const float*)d_in[15];

    int n = in_sizes[0] / IN_DIM;   // 50000
    int E = in_sizes[1] / 2;        // 800000
    const int* src = ei;
    const int* dst = ei + E;

    float* out = (float*)d_out;
    float* out_node   = out;
    float* out_edge   = out + (size_t)n * 3;
    float* out_global = out + (size_t)n * 3 + (size_t)E * 2;
    float* out_value  = out_global + 1;

    float *aggx, *h1, *agg2;
    __half *xh, *h2;
    cudaGetSymbolAddress((void**)&aggx, d_aggx);
    cudaGetSymbolAddress((void**)&h1, d_h1);
    cudaGetSymbolAddress((void**)&agg2, d_agg2);
    cudaGetSymbolAddress((void**)&xh, d_xh);
    cudaGetSymbolAddress((void**)&h2, d_h2);

    int nblk = (n + SCAN_BS - 1) / SCAN_BS;

    // CSR build + x fp16 convert
    k_prep<<<((size_t)n * (IN_DIM / 2) + 255) / 256, 256>>>(x, n);
    k_deg<<<(E + 255) / 256, 256>>>(dst, E);
    k_scan1<<<nblk, SCAN_BS>>>(n);
    k_scan2<<<1, SCAN_BS>>>(nblk);
    k_scan3<<<(n + 255) / 256, 256>>>(n, E);
    k_fill<<<(E + 255) / 256, 256>>>(src, dst, E);

    // Layer 1: gather x (fp16 in), tf32 GEMM (+bias+relu)
    k_gather<IN_DIM, false><<<(n + 7) / 8, 256>>>(xh, aggx, nullptr, n);
    {
        dim3 grid(HID / 128, (n + 127) / 128);
        tgemm128<0><<<grid, 256>>>(n, HID, IN_DIM, aggx, W1, b1, (void*)h1);
    }
    // Layer 2: tf32 GEMM -> fp16 h2, gather (+bias+relu)
    {
        dim3 grid(EMB / 128, (n + 127) / 128);
        tgemm128<1><<<grid, 256>>>(n, EMB, HID, h1, W2, nullptr, (void*)h2);
    }
    k_gather<EMB, true><<<(n + 7) / 8, 256>>>(h2, agg2, b2, n);

    // Heads: pernode (with fused column sums) -> head -> edge
    k_pernode<<<1024, 256>>>(agg2, npW, npb, epW, out_node, n);
    k_head<<<1, 256>>>(fc1W, fc1b, fc2W, fc2b, gpW, gpb, out_global, out_value, 1.0f / (float)n);
    k_edge<<<(E + 255) / 256, 256>>>(src, dst, epb, out_edge, E);
}